// round 6
// baseline (speedup 1.0000x reference)
#include <cuda_runtime.h>
#include <cstddef>

// 2-layer tanh RNN (B=2048,T=512,I=8,H=64)+FC. Weight-stationary registers,
// k-split-8 butterfly reduction. Block=512thr=16warps x 4rows; warp=4b x 8kg.

#define TT 512
#define HS 68   // padded h batch stride (floats)

typedef unsigned long long u64;

static __device__ __forceinline__ void fma2(u64& a, u64 u, u64 v) {
    asm("fma.rn.f32x2 %0, %1, %2, %0;" : "+l"(a) : "l"(u), "l"(v));
}
static __device__ __forceinline__ u64 mul2(u64 u, u64 v) {
    u64 r; asm("mul.rn.f32x2 %0, %1, %2;" : "=l"(r) : "l"(u), "l"(v)); return r;
}
static __device__ __forceinline__ u64 add2(u64 a, u64 b) {
    u64 r; asm("add.rn.f32x2 %0, %1, %2;" : "=l"(r) : "l"(a), "l"(b)); return r;
}
static __device__ __forceinline__ u64 pack2(float a, float b) {
    u64 r; asm("mov.b64 %0, {%1, %2};" : "=l"(r) : "f"(a), "f"(b)); return r;
}
static __device__ __forceinline__ void unpack2(u64 v, float& a, float& b) {
    asm("mov.b64 {%0, %1}, %2;" : "=f"(a), "=f"(b) : "l"(v));
}
static __device__ __forceinline__ float ftanh(float s) {
    const float e = __expf(2.0f * s);
    return 1.0f - __fdividef(2.0f, e + 1.0f);
}

__global__ void __launch_bounds__(512, 1)
rnn_main(const float* __restrict__ x,
         const float* __restrict__ Wih0, const float* __restrict__ Whh0,
         const float* __restrict__ bi0,  const float* __restrict__ bh0,
         const float* __restrict__ Wih1, const float* __restrict__ Whh1,
         const float* __restrict__ bi1,  const float* __restrict__ bh1,
         const float* __restrict__ fcw,  const float* __restrict__ fcb,
         float* __restrict__ out)
{
    __shared__ __align__(16) float h0s[2][4 * HS];
    __shared__ __align__(16) float h1s[2][4 * HS];

    const int tid  = threadIdx.x;
    const int lane = tid & 31;
    const int w    = tid >> 5;     // 16 warps -> rows 4w..4w+3
    const int b    = lane & 3;     // batch within block
    const int kg   = lane >> 2;    // k-group: k in [8kg, 8kg+8)
    const int j0   = w * 4;

    for (int i = tid; i < 4 * HS; i += 512) { h0s[1][i] = 0.f; h1s[1][i] = 0.f; }

    // weights -> registers (k-pair packed)
    u64 wa[4][4], wb[4][4], wc[4][4];
    float w0s[4];
#pragma unroll
    for (int r = 0; r < 4; r++) {
        const int base = ((j0 + r) * 64 + kg * 8) >> 1;   // u64 index
#pragma unroll
        for (int kk = 0; kk < 4; kk++) {
            wa[r][kk] = reinterpret_cast<const u64*>(Whh0)[base + kk];
            wb[r][kk] = reinterpret_cast<const u64*>(Wih1)[base + kk];
            wc[r][kk] = reinterpret_cast<const u64*>(Whh1)[base + kk];
        }
        w0s[r] = Wih0[(j0 + r) * 8 + kg];    // x-term weight, i = kg
    }
    const u64 bv00 = pack2(bi0[j0]   + bh0[j0],   bi0[j0+1] + bh0[j0+1]);
    const u64 bv01 = pack2(bi0[j0+2] + bh0[j0+2], bi0[j0+3] + bh0[j0+3]);
    const u64 bv10 = pack2(bi1[j0]   + bh1[j0],   bi1[j0+1] + bh1[j0+1]);
    const u64 bv11 = pack2(bi1[j0+2] + bh1[j0+2], bi1[j0+3] + bh1[j0+3]);

    const float* xp = x + ((size_t)(blockIdx.x * 4 + b) * TT) * 8 + kg;
    float xc = xp[0];

    const int hrd = b * HS + kg * 8;   // read offset (floats), 16B aligned
    const int hwr = b * HS + j0;       // write offset (kg==0 lanes)

    __syncthreads();

#pragma unroll 1
    for (int t = 0; t < TT; t++) {
        const int p = t & 1, pq = p ^ 1;
        const int tn = (t + 1 < TT) ? (t + 1) : t;
        const float xn = xp[tn * 8];

        // ---------------- layer 0: Whh0 @ h0_prev + Wih0 @ x ----------------
        u64 a0, a1, a2, a3;
        {
            const ulonglong2* hu = reinterpret_cast<const ulonglong2*>(&h0s[pq][hrd]);
            const ulonglong2 u0 = hu[0], u1 = hu[1];
            a0 = mul2(wa[0][0], u0.x); fma2(a0, wa[0][1], u0.y); fma2(a0, wa[0][2], u1.x); fma2(a0, wa[0][3], u1.y);
            a1 = mul2(wa[1][0], u0.x); fma2(a1, wa[1][1], u0.y); fma2(a1, wa[1][2], u1.x); fma2(a1, wa[1][3], u1.y);
            a2 = mul2(wa[2][0], u0.x); fma2(a2, wa[2][1], u0.y); fma2(a2, wa[2][2], u1.x); fma2(a2, wa[2][3], u1.y);
            a3 = mul2(wa[3][0], u0.x); fma2(a3, wa[3][1], u0.y); fma2(a3, wa[3][2], u1.x); fma2(a3, wa[3][3], u1.y);
        }
        {
            float e0, f0, e1, f1, e2, f2, e3, f3;
            unpack2(a0, e0, f0); unpack2(a1, e1, f1);
            unpack2(a2, e2, f2); unpack2(a3, e3, f3);
            u64 v0 = pack2(fmaf(w0s[0], xc, e0 + f0), fmaf(w0s[1], xc, e1 + f1));
            u64 v1 = pack2(fmaf(w0s[2], xc, e2 + f2), fmaf(w0s[3], xc, e3 + f3));
            v0 = add2(v0, __shfl_xor_sync(0xffffffffu, v0, 4));
            v1 = add2(v1, __shfl_xor_sync(0xffffffffu, v1, 4));
            v0 = add2(v0, __shfl_xor_sync(0xffffffffu, v0, 8));
            v1 = add2(v1, __shfl_xor_sync(0xffffffffu, v1, 8));
            v0 = add2(v0, __shfl_xor_sync(0xffffffffu, v0, 16));
            v1 = add2(v1, __shfl_xor_sync(0xffffffffu, v1, 16));
            v0 = add2(v0, bv00);
            v1 = add2(v1, bv01);
            if (kg == 0) {
                float s0, s1, s2, s3;
                unpack2(v0, s0, s1); unpack2(v1, s2, s3);
                float4 o;
                o.x = ftanh(s0); o.y = ftanh(s1); o.z = ftanh(s2); o.w = ftanh(s3);
                *reinterpret_cast<float4*>(&h0s[p][hwr]) = o;
            }
        }
        __syncthreads();   // single per-step barrier

        // ---------- layer 1: Wih1 @ h0_new + Whh1 @ h1_prev ----------
        {
            const ulonglong2* g0 = reinterpret_cast<const ulonglong2*>(&h0s[p][hrd]);
            const ulonglong2 u0 = g0[0], u1 = g0[1];
            a0 = mul2(wb[0][0], u0.x); fma2(a0, wb[0][1], u0.y); fma2(a0, wb[0][2], u1.x); fma2(a0, wb[0][3], u1.y);
            a1 = mul2(wb[1][0], u0.x); fma2(a1, wb[1][1], u0.y); fma2(a1, wb[1][2], u1.x); fma2(a1, wb[1][3], u1.y);
            a2 = mul2(wb[2][0], u0.x); fma2(a2, wb[2][1], u0.y); fma2(a2, wb[2][2], u1.x); fma2(a2, wb[2][3], u1.y);
            a3 = mul2(wb[3][0], u0.x); fma2(a3, wb[3][1], u0.y); fma2(a3, wb[3][2], u1.x); fma2(a3, wb[3][3], u1.y);
            const ulonglong2* g1 = reinterpret_cast<const ulonglong2*>(&h1s[pq][hrd]);
            const ulonglong2 z0 = g1[0], z1 = g1[1];
            fma2(a0, wc[0][0], z0.x); fma2(a0, wc[0][1], z0.y); fma2(a0, wc[0][2], z1.x); fma2(a0, wc[0][3], z1.y);
            fma2(a1, wc[1][0], z0.x); fma2(a1, wc[1][1], z0.y); fma2(a1, wc[1][2], z1.x); fma2(a1, wc[1][3], z1.y);
            fma2(a2, wc[2][0], z0.x); fma2(a2, wc[2][1], z0.y); fma2(a2, wc[2][2], z1.x); fma2(a2, wc[2][3], z1.y);
            fma2(a3, wc[3][0], z0.x); fma2(a3, wc[3][1], z0.y); fma2(a3, wc[3][2], z1.x); fma2(a3, wc[3][3], z1.y);
        }
        {
            float e0, f0, e1, f1, e2, f2, e3, f3;
            unpack2(a0, e0, f0); unpack2(a1, e1, f1);
            unpack2(a2, e2, f2); unpack2(a3, e3, f3);
            u64 v0 = pack2(e0 + f0, e1 + f1);
            u64 v1 = pack2(e2 + f2, e3 + f3);
            v0 = add2(v0, __shfl_xor_sync(0xffffffffu, v0, 4));
            v1 = add2(v1, __shfl_xor_sync(0xffffffffu, v1, 4));
            v0 = add2(v0, __shfl_xor_sync(0xffffffffu, v0, 8));
            v1 = add2(v1, __shfl_xor_sync(0xffffffffu, v1, 8));
            v0 = add2(v0, __shfl_xor_sync(0xffffffffu, v0, 16));
            v1 = add2(v1, __shfl_xor_sync(0xffffffffu, v1, 16));
            v0 = add2(v0, bv10);
            v1 = add2(v1, bv11);
            if (kg == 0) {
                float s0, s1, s2, s3;
                unpack2(v0, s0, s1); unpack2(v1, s2, s3);
                float4 o;
                o.x = ftanh(s0); o.y = ftanh(s1); o.z = ftanh(s2); o.w = ftanh(s3);
                *reinterpret_cast<float4*>(&h1s[p][hwr]) = o;
            }
        }
        xc = xn;
        // next step's mid barrier orders this step's h1 writes vs its reads
    }

    __syncthreads();

    // FC: out[b] = h1_final . fcw + fcb ; final parity = (TT-1)&1 = 1
    if (tid < 4) {
        float sum = fcb[0];
        const float* hp = &h1s[1][tid * HS];
#pragma unroll
        for (int q = 0; q < 16; q++) {
            const float4 hv = *reinterpret_cast<const float4*>(hp + q * 4);
            const float4 wv = reinterpret_cast<const float4*>(fcw)[q];
            sum += hv.x * wv.x + hv.y * wv.y + hv.z * wv.z + hv.w * wv.w;
        }
        out[blockIdx.x * 4 + tid] = sum;
    }
}

extern "C" void kernel_launch(void* const* d_in, const int* in_sizes, int n_in,
                              void* d_out, int out_size)
{
    // Inputs: x, W_ih0, W_hh0, b_ih0, b_hh0, W_ih1, W_hh1, b_ih1, b_hh1, fc_w, fc_b
    (void)in_sizes; (void)n_in; (void)out_size;
    rnn_main<<<512, 512>>>(
        (const float*)d_in[0],
        (const float*)d_in[1], (const float*)d_in[2],
        (const float*)d_in[3], (const float*)d_in[4],
        (const float*)d_in[5], (const float*)d_in[6],
        (const float*)d_in[7], (const float*)d_in[8],
        (const float*)d_in[9], (const float*)d_in[10],
        (float*)d_out);
}

// round 7
// speedup vs baseline: 1.6048x; 1.6048x over previous
#include <cuda_runtime.h>
#include <cstddef>

// 2-layer tanh RNN (B=2048,T=512,I=8,H=64)+FC.
// R6: weight-stationary registers, k-split-8, 4 batches/thread, grid 128 = 1 wave.
// Block 512 = 16 warps x 4 rows; lanes = 4 batch-lanes x 8 k-groups.
// Reduction: distributing round (slot-permuted, no selects) + 2 butterfly rounds.

#define TT 512
#define HS 68

typedef unsigned long long u64;

static __device__ __forceinline__ void fma2(u64& a, u64 u, u64 v) {
    asm("fma.rn.f32x2 %0, %1, %2, %0;" : "+l"(a) : "l"(u), "l"(v));
}
static __device__ __forceinline__ u64 mul2(u64 u, u64 v) {
    u64 r; asm("mul.rn.f32x2 %0, %1, %2;" : "=l"(r) : "l"(u), "l"(v)); return r;
}
static __device__ __forceinline__ u64 add2(u64 a, u64 b) {
    u64 r; asm("add.rn.f32x2 %0, %1, %2;" : "=l"(r) : "l"(a), "l"(b)); return r;
}
static __device__ __forceinline__ u64 pack2(float a, float b) {
    u64 r; asm("mov.b64 %0, {%1, %2};" : "=l"(r) : "f"(a), "f"(b)); return r;
}
static __device__ __forceinline__ void unpack2(u64 v, float& a, float& b) {
    asm("mov.b64 {%0, %1}, %2;" : "=f"(a), "=f"(b) : "l"(v));
}
static __device__ __forceinline__ u64 dup2(float a) {
    u64 r; asm("mov.b64 %0, {%1, %1};" : "=l"(r) : "f"(a)); return r;
}
static __device__ __forceinline__ float ftanh(float s) {
    const float e = __expf(2.0f * s);
    return 1.0f - __fdividef(2.0f, e + 1.0f);
}
static __device__ __forceinline__ u64 shx(u64 v, int m) {
    return __shfl_xor_sync(0xffffffffu, v, m, 32);
}

__global__ void __launch_bounds__(512, 1)
rnn_main(const float* __restrict__ x,
         const float* __restrict__ Wih0, const float* __restrict__ Whh0,
         const float* __restrict__ bi0,  const float* __restrict__ bh0,
         const float* __restrict__ Wih1, const float* __restrict__ Whh1,
         const float* __restrict__ bi1,  const float* __restrict__ bh1,
         const float* __restrict__ fcw,  const float* __restrict__ fcb,
         float* __restrict__ out)
{
    __shared__ __align__(16) float h0s[2][16 * HS];
    __shared__ __align__(16) float h1s[2][16 * HS];

    const int tid  = threadIdx.x;
    const int lane = tid & 31;
    const int w    = tid >> 5;      // 16 warps -> rows j0..j0+3
    const int b    = lane & 3;      // batch lane
    const int kg   = lane >> 2;     // k-group: k in [8kg, 8kg+8)
    const int s    = kg & 1;        // slot-permute bit (owned row-pair = s)
    const int j0   = w * 4;

    for (int i = tid; i < 16 * HS; i += 512) { h0s[1][i] = 0.f; h1s[1][i] = 0.f; }

    // Weights in registers. Acc slot q covers physical row-pair (q^s):
    // rows jr(q,h) = j0 + 2*(q^s) + h. k-pair packed along k.
    u64 wa[2][2][4], wb[2][2][4], wc[2][2][4], wxp[2];
#pragma unroll
    for (int q = 0; q < 2; q++) {
        const int jA = j0 + 2 * (q ^ s);
#pragma unroll
        for (int h = 0; h < 2; h++) {
            const int base = ((jA + h) * 64 + kg * 8) >> 1;   // u64 index
#pragma unroll
            for (int kk = 0; kk < 4; kk++) {
                wa[q][h][kk] = reinterpret_cast<const u64*>(Whh0)[base + kk];
                wb[q][h][kk] = reinterpret_cast<const u64*>(Wih1)[base + kk];
                wc[q][h][kk] = reinterpret_cast<const u64*>(Whh1)[base + kk];
            }
        }
        wxp[q] = pack2(Wih0[jA * 8 + kg], Wih0[(jA + 1) * 8 + kg]);
    }
    // biases for the owned pair (rows j0+2s, j0+2s+1)
    const u64 bz0 = pack2(bi0[j0+2*s] + bh0[j0+2*s], bi0[j0+2*s+1] + bh0[j0+2*s+1]);
    const u64 bz1 = pack2(bi1[j0+2*s] + bh1[j0+2*s], bi1[j0+2*s+1] + bh1[j0+2*s+1]);

    // x base for this lane: batch chunk bi -> xpb[bi*4*TT*8 + t*8]
    const float* xpb = x + ((size_t)(blockIdx.x * 16 + b) * TT) * 8 + kg;

    const int sto = ((kg >> 1) * 4 + b) * HS + j0 + 2 * s;  // owned store offset
    const int mychunk = kg >> 1;

    __syncthreads();

#pragma unroll 1
    for (int t = 0; t < TT; t++) {
        const int p = t & 1, pq = p ^ 1;

        float xv[4];
#pragma unroll
        for (int bi = 0; bi < 4; bi++) xv[bi] = xpb[((size_t)bi * 4 * TT + t) * 8];

        // ---------------- layer 0 ----------------
        u64 keep0;
#pragma unroll
        for (int bi = 0; bi < 4; bi++) {
            const ulonglong2* hp =
                reinterpret_cast<const ulonglong2*>(&h0s[pq][(bi * 4 + b) * HS + kg * 8]);
            const ulonglong2 u0 = hp[0], u1 = hp[1];
            u64 a[2][2];
#pragma unroll
            for (int q = 0; q < 2; q++)
#pragma unroll
                for (int h = 0; h < 2; h++) {
                    a[q][h] = mul2(wa[q][h][0], u0.x);
                    fma2(a[q][h], wa[q][h][1], u0.y);
                    fma2(a[q][h], wa[q][h][2], u1.x);
                    fma2(a[q][h], wa[q][h][3], u1.y);
                }
            // horizontal + x-term -> v[q] packed over the pair's 2 rows
            u64 v[2];
            const u64 xd = dup2(xv[bi]);
#pragma unroll
            for (int q = 0; q < 2; q++) {
                float l0, h0, l1, h1;
                unpack2(a[q][0], l0, h0); unpack2(a[q][1], l1, h1);
                v[q] = pack2(l0 + h0, l1 + h1);
                fma2(v[q], wxp[q], xd);
            }
            // reduction: distributing round (xor 4), then butterflies (8, 16)
            u64 r = add2(v[0], shx(v[1], 4));
            r = add2(r, shx(r, 8));
            r = add2(r, shx(r, 16));
            if (mychunk == bi) keep0 = r;
        }
        {
            keep0 = add2(keep0, bz0);
            float f0, f1;
            unpack2(keep0, f0, f1);
            *reinterpret_cast<u64*>(&h0s[p][sto]) = pack2(ftanh(f0), ftanh(f1));
        }
        __syncthreads();   // the single per-step barrier

        // ---------------- layer 1 ----------------
        u64 keep1;
#pragma unroll
        for (int bi = 0; bi < 4; bi++) {
            const int ho = (bi * 4 + b) * HS + kg * 8;
            const ulonglong2* g0 = reinterpret_cast<const ulonglong2*>(&h0s[p][ho]);
            const ulonglong2 u0 = g0[0], u1 = g0[1];
            u64 a[2][2];
#pragma unroll
            for (int q = 0; q < 2; q++)
#pragma unroll
                for (int h = 0; h < 2; h++) {
                    a[q][h] = mul2(wb[q][h][0], u0.x);
                    fma2(a[q][h], wb[q][h][1], u0.y);
                    fma2(a[q][h], wb[q][h][2], u1.x);
                    fma2(a[q][h], wb[q][h][3], u1.y);
                }
            const ulonglong2* g1 = reinterpret_cast<const ulonglong2*>(&h1s[pq][ho]);
            const ulonglong2 z0 = g1[0], z1 = g1[1];
#pragma unroll
            for (int q = 0; q < 2; q++)
#pragma unroll
                for (int h = 0; h < 2; h++) {
                    fma2(a[q][h], wc[q][h][0], z0.x);
                    fma2(a[q][h], wc[q][h][1], z0.y);
                    fma2(a[q][h], wc[q][h][2], z1.x);
                    fma2(a[q][h], wc[q][h][3], z1.y);
                }
            u64 v[2];
#pragma unroll
            for (int q = 0; q < 2; q++) {
                float l0, h0, l1, h1;
                unpack2(a[q][0], l0, h0); unpack2(a[q][1], l1, h1);
                v[q] = pack2(l0 + h0, l1 + h1);
            }
            u64 r = add2(v[0], shx(v[1], 4));
            r = add2(r, shx(r, 8));
            r = add2(r, shx(r, 16));
            if (mychunk == bi) keep1 = r;
        }
        {
            keep1 = add2(keep1, bz1);
            float f0, f1;
            unpack2(keep1, f0, f1);
            *reinterpret_cast<u64*>(&h1s[p][sto]) = pack2(ftanh(f0), ftanh(f1));
        }
        // next step's mid barrier orders these h1 writes vs their readers
    }

    __syncthreads();

    // FC: out[b] = h1_final . fcw + fcb ; final parity = (TT-1)&1 = 1
    if (tid < 16) {
        float sum = fcb[0];
        const float* hp = &h1s[1][tid * HS];
#pragma unroll
        for (int q = 0; q < 16; q++) {
            const float4 hv = *reinterpret_cast<const float4*>(hp + q * 4);
            const float4 wv = reinterpret_cast<const float4*>(fcw)[q];
            sum += hv.x * wv.x + hv.y * wv.y + hv.z * wv.z + hv.w * wv.w;
        }
        out[blockIdx.x * 16 + tid] = sum;
    }
}

extern "C" void kernel_launch(void* const* d_in, const int* in_sizes, int n_in,
                              void* d_out, int out_size)
{
    // Inputs: x, W_ih0, W_hh0, b_ih0, b_hh0, W_ih1, W_hh1, b_ih1, b_hh1, fc_w, fc_b
    (void)in_sizes; (void)n_in; (void)out_size;
    rnn_main<<<128, 512>>>(
        (const float*)d_in[0],
        (const float*)d_in[1], (const float*)d_in[2],
        (const float*)d_in[3], (const float*)d_in[4],
        (const float*)d_in[5], (const float*)d_in[6],
        (const float*)d_in[7], (const float*)d_in[8],
        (const float*)d_in[9], (const float*)d_in[10],
        (float*)d_out);
}

// round 8
// speedup vs baseline: 2.0052x; 1.2495x over previous
#include <cuda_runtime.h>
#include <cstddef>

// 2-layer tanh RNN (B=2048,T=512,I=8,H=64)+FC.
// R7: R6 + conflict-free h layout. Weight-stationary registers, k-split-8,
// 4 batches/thread, grid 128 = 1 wave. h stored as 16 quads/batch with quad
// rotation g(B) = (B&1)|((B&2)<<1); read banks provably all-distinct per phase.

#define TT 512

typedef unsigned long long u64;

static __device__ __forceinline__ void fma2(u64& a, u64 u, u64 v) {
    asm("fma.rn.f32x2 %0, %1, %2, %0;" : "+l"(a) : "l"(u), "l"(v));
}
static __device__ __forceinline__ u64 mul2(u64 u, u64 v) {
    u64 r; asm("mul.rn.f32x2 %0, %1, %2;" : "=l"(r) : "l"(u), "l"(v)); return r;
}
static __device__ __forceinline__ u64 add2(u64 a, u64 b) {
    u64 r; asm("add.rn.f32x2 %0, %1, %2;" : "=l"(r) : "l"(a), "l"(b)); return r;
}
static __device__ __forceinline__ u64 pack2(float a, float b) {
    u64 r; asm("mov.b64 %0, {%1, %2};" : "=l"(r) : "f"(a), "f"(b)); return r;
}
static __device__ __forceinline__ void unpack2(u64 v, float& a, float& b) {
    asm("mov.b64 {%0, %1}, %2;" : "=f"(a), "=f"(b) : "l"(v));
}
static __device__ __forceinline__ u64 dup2(float a) {
    u64 r; asm("mov.b64 %0, {%1, %1};" : "=l"(r) : "f"(a)); return r;
}
static __device__ __forceinline__ float ftanh(float s) {
    const float e = __expf(2.0f * s);
    return 1.0f - __fdividef(2.0f, e + 1.0f);
}
static __device__ __forceinline__ u64 shx(u64 v, int m) {
    return __shfl_xor_sync(0xffffffffu, v, m, 32);
}

__global__ void __launch_bounds__(512, 1)
rnn_main(const float* __restrict__ x,
         const float* __restrict__ Wih0, const float* __restrict__ Whh0,
         const float* __restrict__ bi0,  const float* __restrict__ bh0,
         const float* __restrict__ Wih1, const float* __restrict__ Whh1,
         const float* __restrict__ bi1,  const float* __restrict__ bh1,
         const float* __restrict__ fcw,  const float* __restrict__ fcb,
         float* __restrict__ out)
{
    // h: [parity][batch 0..15][quad-slot 0..15] float4s; quad q of batch B
    // lives at slot (q + g(B)) & 15, g(B) = (B&1)|((B&2)<<1).
    __shared__ __align__(16) float h0s[2][16 * 64];
    __shared__ __align__(16) float h1s[2][16 * 64];

    const int tid  = threadIdx.x;
    const int lane = tid & 31;
    const int w    = tid >> 5;      // 16 warps -> rows j0..j0+3
    const int b    = lane & 3;      // batch lane (B mod 4 == b)
    const int kg   = lane >> 2;     // k-group: k in [8kg, 8kg+8)
    const int s    = kg & 1;        // slot-permute bit (owned row-pair = s)
    const int j0   = w * 4;
    const int g    = (b & 1) | ((b & 2) << 1);   // quad rotation for this b

    for (int i = tid; i < 16 * 64; i += 512) { h0s[1][i] = 0.f; h1s[1][i] = 0.f; }

    // Precomputed conflict-free read offsets (floats): chunk bi, quads 2kg,2kg+1
    int ofA[4], ofB[4];
#pragma unroll
    for (int bi = 0; bi < 4; bi++) {
        const int B = bi * 4 + b;
        ofA[bi] = B * 64 + (((2 * kg     + g) & 15) << 2);
        ofB[bi] = B * 64 + (((2 * kg + 1 + g) & 15) << 2);
    }
    // Owned store offset: batch Bm = mychunk*4+b, rows j0+2s (quad j0>>2... = w)
    const int mychunk = kg >> 1;
    const int sto = (mychunk * 4 + b) * 64 + (((w + g) & 15) << 2) + 2 * s;

    // Weights in registers. Acc slot q covers physical row-pair (q^s).
    u64 wa[2][2][4], wb[2][2][4], wc[2][2][4], wxp[2];
#pragma unroll
    for (int q = 0; q < 2; q++) {
        const int jA = j0 + 2 * (q ^ s);
#pragma unroll
        for (int h = 0; h < 2; h++) {
            const int base = ((jA + h) * 64 + kg * 8) >> 1;   // u64 index
#pragma unroll
            for (int kk = 0; kk < 4; kk++) {
                wa[q][h][kk] = reinterpret_cast<const u64*>(Whh0)[base + kk];
                wb[q][h][kk] = reinterpret_cast<const u64*>(Wih1)[base + kk];
                wc[q][h][kk] = reinterpret_cast<const u64*>(Whh1)[base + kk];
            }
        }
        wxp[q] = pack2(Wih0[jA * 8 + kg], Wih0[(jA + 1) * 8 + kg]);
    }
    const u64 bz0 = pack2(bi0[j0+2*s] + bh0[j0+2*s], bi0[j0+2*s+1] + bh0[j0+2*s+1]);
    const u64 bz1 = pack2(bi1[j0+2*s] + bh1[j0+2*s], bi1[j0+2*s+1] + bh1[j0+2*s+1]);

    const float* xpb = x + ((size_t)(blockIdx.x * 16 + b) * TT) * 8 + kg;

    __syncthreads();

#pragma unroll 1
    for (int t = 0; t < TT; t++) {
        const int p = t & 1, pq = p ^ 1;

        float xv[4];
#pragma unroll
        for (int bi = 0; bi < 4; bi++) xv[bi] = xpb[((size_t)bi * 4 * TT + t) * 8];

        // ---------------- layer 0 ----------------
        u64 keep0;
#pragma unroll
        for (int bi = 0; bi < 4; bi++) {
            const u64* qa = reinterpret_cast<const u64*>(&h0s[pq][ofA[bi]]);
            const u64* qb = reinterpret_cast<const u64*>(&h0s[pq][ofB[bi]]);
            const u64 h0 = qa[0], h1 = qa[1], h2 = qb[0], h3 = qb[1];
            u64 a[2][2];
#pragma unroll
            for (int q = 0; q < 2; q++)
#pragma unroll
                for (int h = 0; h < 2; h++) {
                    a[q][h] = mul2(wa[q][h][0], h0);
                    fma2(a[q][h], wa[q][h][1], h1);
                    fma2(a[q][h], wa[q][h][2], h2);
                    fma2(a[q][h], wa[q][h][3], h3);
                }
            u64 v[2];
            const u64 xd = dup2(xv[bi]);
#pragma unroll
            for (int q = 0; q < 2; q++) {
                float l0, m0, l1, m1;
                unpack2(a[q][0], l0, m0); unpack2(a[q][1], l1, m1);
                v[q] = pack2(l0 + m0, l1 + m1);
                fma2(v[q], wxp[q], xd);
            }
            u64 r = add2(v[0], shx(v[1], 4));
            r = add2(r, shx(r, 8));
            r = add2(r, shx(r, 16));
            if (mychunk == bi) keep0 = r;
        }
        {
            keep0 = add2(keep0, bz0);
            float f0, f1;
            unpack2(keep0, f0, f1);
            *reinterpret_cast<u64*>(&h0s[p][sto]) = pack2(ftanh(f0), ftanh(f1));
        }
        __syncthreads();   // the single per-step barrier

        // ---------------- layer 1 ----------------
        u64 keep1;
#pragma unroll
        for (int bi = 0; bi < 4; bi++) {
            const u64* qa0 = reinterpret_cast<const u64*>(&h0s[p][ofA[bi]]);
            const u64* qb0 = reinterpret_cast<const u64*>(&h0s[p][ofB[bi]]);
            const u64 u0 = qa0[0], u1 = qa0[1], u2 = qb0[0], u3 = qb0[1];
            u64 a[2][2];
#pragma unroll
            for (int q = 0; q < 2; q++)
#pragma unroll
                for (int h = 0; h < 2; h++) {
                    a[q][h] = mul2(wb[q][h][0], u0);
                    fma2(a[q][h], wb[q][h][1], u1);
                    fma2(a[q][h], wb[q][h][2], u2);
                    fma2(a[q][h], wb[q][h][3], u3);
                }
            const u64* qa1 = reinterpret_cast<const u64*>(&h1s[pq][ofA[bi]]);
            const u64* qb1 = reinterpret_cast<const u64*>(&h1s[pq][ofB[bi]]);
            const u64 z0 = qa1[0], z1 = qa1[1], z2 = qb1[0], z3 = qb1[1];
#pragma unroll
            for (int q = 0; q < 2; q++)
#pragma unroll
                for (int h = 0; h < 2; h++) {
                    fma2(a[q][h], wc[q][h][0], z0);
                    fma2(a[q][h], wc[q][h][1], z1);
                    fma2(a[q][h], wc[q][h][2], z2);
                    fma2(a[q][h], wc[q][h][3], z3);
                }
            u64 v[2];
#pragma unroll
            for (int q = 0; q < 2; q++) {
                float l0, m0, l1, m1;
                unpack2(a[q][0], l0, m0); unpack2(a[q][1], l1, m1);
                v[q] = pack2(l0 + m0, l1 + m1);
            }
            u64 r = add2(v[0], shx(v[1], 4));
            r = add2(r, shx(r, 8));
            r = add2(r, shx(r, 16));
            if (mychunk == bi) keep1 = r;
        }
        {
            keep1 = add2(keep1, bz1);
            float f0, f1;
            unpack2(keep1, f0, f1);
            *reinterpret_cast<u64*>(&h1s[p][sto]) = pack2(ftanh(f0), ftanh(f1));
        }
        // next step's mid barrier orders these h1 writes vs their readers
    }

    __syncthreads();

    // FC: out[b] = h1_final . fcw + fcb ; final parity = (TT-1)&1 = 1
    if (tid < 16) {
        const int gg = (tid & 1) | ((tid & 2) << 1);
        float sum = fcb[0];
#pragma unroll
        for (int q = 0; q < 16; q++) {
            const float4 hv = *reinterpret_cast<const float4*>(
                &h1s[1][tid * 64 + (((q + gg) & 15) << 2)]);
            const float4 wv = reinterpret_cast<const float4*>(fcw)[q];
            sum += hv.x * wv.x + hv.y * wv.y + hv.z * wv.z + hv.w * wv.w;
        }
        out[blockIdx.x * 16 + tid] = sum;
    }
}

extern "C" void kernel_launch(void* const* d_in, const int* in_sizes, int n_in,
                              void* d_out, int out_size)
{
    // Inputs: x, W_ih0, W_hh0, b_ih0, b_hh0, W_ih1, W_hh1, b_ih1, b_hh1, fc_w, fc_b
    (void)in_sizes; (void)n_in; (void)out_size;
    rnn_main<<<128, 512>>>(
        (const float*)d_in[0],
        (const float*)d_in[1], (const float*)d_in[2],
        (const float*)d_in[3], (const float*)d_in[4],
        (const float*)d_in[5], (const float*)d_in[6],
        (const float*)d_in[7], (const float*)d_in[8],
        (const float*)d_in[9], (const float*)d_in[10],
        (float*)d_out);
}